// round 2
// baseline (speedup 1.0000x reference)
#include <cuda_runtime.h>

#define BB 4
#define HH 16
#define SS 2048
#define DKK 64
#define DVV 64

#define SBLK 16        // q rows per CTA
#define KTILE 256      // keys staged per smem tile
#define NTHREADS 256
#define KV_STRIDE 80   // floats; 80/4=20 bank-units -> disjoint LDS.128 wavefronts

// smem (floats): p_s[16][2048] + q_s[16][80] + kv_s[256][80]
#define SMEM_FLOATS (SBLK * SS + SBLK * KV_STRIDE + KTILE * KV_STRIDE)

typedef unsigned long long u64;

__device__ __forceinline__ void fma2(u64& acc, u64 a, u64 b) {
    asm("fma.rn.f32x2 %0, %1, %2, %0;" : "+l"(acc) : "l"(a), "l"(b));
}
__device__ __forceinline__ u64 dup2(float s) {
    u64 d;
    asm("mov.b64 %0, {%1, %1};" : "=l"(d) : "f"(s));
    return d;
}
__device__ __forceinline__ float2 unpack2(u64 a) {
    float x, y;
    asm("mov.b64 {%0, %1}, %2;" : "=f"(x), "=f"(y) : "l"(a));
    return make_float2(x, y);
}

__global__ __launch_bounds__(NTHREADS, 1)
void psdpa_kernel(const float* __restrict__ q,
                  const float* __restrict__ k,
                  const float* __restrict__ v,
                  const int* __restrict__ mask,
                  float* __restrict__ out,
                  float* __restrict__ attn)
{
    extern __shared__ float smem[];
    float* p_s  = smem;                          // [SBLK][SS]
    float* q_s  = smem + SBLK * SS;              // [SBLK][KV_STRIDE]
    float* kv_s = q_s + SBLK * KV_STRIDE;        // [KTILE][KV_STRIDE]

    const int tid  = threadIdx.x;
    const int w    = tid >> 5;
    const int lane = tid & 31;

    const int bh = blockIdx.y;
    const int b  = bh >> 4;
    const int q0 = blockIdx.x * SBLK;

    const float* qbase = q + (size_t)bh * SS * DKK + (size_t)q0 * DKK;
    const float* kbase = k + (size_t)bh * SS * DKK;
    const float* vbase = v + (size_t)bh * SS * DVV;

    // ---- load Q block (scaled by 1/8), row-major with KV_STRIDE padding ----
    {
        const float4* qg = (const float4*)qbase;       // 256 float4
        float4 t = qg[tid];
        int row = tid >> 4;
        int d4  = (tid & 15) << 2;
        t.x *= 0.125f; t.y *= 0.125f; t.z *= 0.125f; t.w *= 0.125f;
        *(float4*)(q_s + row * KV_STRIDE + d4) = t;
    }

    // QK lane mapping: rg in 0..3 (rows rg+4j), kg in 0..7 (keys kg+8i within warp's 32)
    const int rg = lane >> 3;
    const int kg = lane & 7;

    // =========================== QK^T (FFMA2, d-packed) ===========================
    for (int kt = 0; kt < SS / KTILE; ++kt) {
        __syncthreads();
        {   // stage K tile coalesced
            const float4* kgm = (const float4*)(kbase + (size_t)kt * KTILE * DKK);
            #pragma unroll
            for (int it = 0; it < (KTILE * DKK / 4) / NTHREADS; ++it) {  // 16
                int idx = tid + it * NTHREADS;
                int key = idx >> 4;
                int d4  = (idx & 15) << 2;
                *(float4*)(kv_s + key * KV_STRIDE + d4) = kgm[idx];
            }
        }
        __syncthreads();

        u64 acc[4][4];
        #pragma unroll
        for (int j = 0; j < 4; ++j)
            #pragma unroll
            for (int i = 0; i < 4; ++i) acc[j][i] = 0ull;

        const float* qp = q_s + rg * KV_STRIDE;                 // rows rg + 4j
        const float* kp = kv_s + (w * 32 + kg) * KV_STRIDE;     // keys +8i

        #pragma unroll 4
        for (int d = 0; d < DKK; d += 4) {
            ulonglong2 qv[4], kv[4];
            #pragma unroll
            for (int j = 0; j < 4; ++j)
                qv[j] = *(const ulonglong2*)(qp + (4 * j) * KV_STRIDE + d);
            #pragma unroll
            for (int i = 0; i < 4; ++i)
                kv[i] = *(const ulonglong2*)(kp + (8 * i) * KV_STRIDE + d);
            #pragma unroll
            for (int j = 0; j < 4; ++j)
                #pragma unroll
                for (int i = 0; i < 4; ++i) {
                    fma2(acc[j][i], qv[j].x, kv[i].x);
                    fma2(acc[j][i], qv[j].y, kv[i].y);
                }
        }

        // epilogue: score = even-sum + odd-sum
        #pragma unroll
        for (int j = 0; j < 4; ++j) {
            float* prow = p_s + (rg + 4 * j) * SS + kt * KTILE + w * 32 + kg;
            #pragma unroll
            for (int i = 0; i < 4; ++i) {
                float2 s = unpack2(acc[j][i]);
                prow[8 * i] = s.x + s.y;
            }
        }
    }
    __syncthreads();

    // ====================== mask + softmax + attn store ======================
    #pragma unroll
    for (int rr = 0; rr < 2; ++rr) {
        int r    = 2 * w + rr;
        int qrow = q0 + r;
        const int* mrow = mask + (size_t)b * SS * SS + (size_t)qrow * SS;
        float* prow = p_s + r * SS;
        float* arow = attn + (size_t)bh * SS * SS + (size_t)qrow * SS;

        float vmax = -3.4e38f;
        for (int jj = lane; jj < SS; jj += 32) {
            float s = prow[jj];
            s = (mrow[jj] != 0) ? s : -1.0e9f;
            prow[jj] = s;
            vmax = fmaxf(vmax, s);
        }
        #pragma unroll
        for (int o = 16; o > 0; o >>= 1)
            vmax = fmaxf(vmax, __shfl_xor_sync(0xffffffffu, vmax, o));

        float sum = 0.f;
        for (int jj = lane; jj < SS; jj += 32) {
            float e = __expf(prow[jj] - vmax);
            prow[jj] = e;
            sum += e;
        }
        #pragma unroll
        for (int o = 16; o > 0; o >>= 1)
            sum += __shfl_xor_sync(0xffffffffu, sum, o);
        float inv = 1.0f / sum;

        for (int jj = lane; jj < SS; jj += 32) {
            float pv = prow[jj] * inv;
            prow[jj] = pv;
            arow[jj] = pv;
        }
    }

    // =========================== P @ V (FFMA2, dim-packed) ===========================
    // warp w owns rows {2w, 2w+1}; lanes: kgv = lane>>2 (keys +8 apart), dg = lane&3 (16 dims)
    const int kgv = lane >> 2;
    const int dg  = lane & 3;

    u64 acc[2][8];
    #pragma unroll
    for (int r = 0; r < 2; ++r)
        #pragma unroll
        for (int p = 0; p < 8; ++p) acc[r][p] = 0ull;

    for (int vt = 0; vt < SS / KTILE; ++vt) {
        __syncthreads();
        {   // stage V tile coalesced (reuse kv_s)
            const float4* vgm = (const float4*)(vbase + (size_t)vt * KTILE * DVV);
            #pragma unroll
            for (int it = 0; it < (KTILE * DVV / 4) / NTHREADS; ++it) {
                int idx = tid + it * NTHREADS;
                int key = idx >> 4;
                int d4  = (idx & 15) << 2;
                *(float4*)(kv_s + key * KV_STRIDE + d4) = vgm[idx];
            }
        }
        __syncthreads();

        const float* p0 = p_s + (2 * w) * SS + vt * KTILE;
        const float* p1 = p0 + SS;

        #pragma unroll 4
        for (int kk = 0; kk < KTILE; kk += 8) {
            int key = kk + kgv;
            u64 pa = dup2(p0[key]);
            u64 pb = dup2(p1[key]);
            const float* vp = kv_s + key * KV_STRIDE + dg * 16;
            ulonglong2 v0 = *(const ulonglong2*)(vp + 0);
            ulonglong2 v1 = *(const ulonglong2*)(vp + 4);
            ulonglong2 v2 = *(const ulonglong2*)(vp + 8);
            ulonglong2 v3 = *(const ulonglong2*)(vp + 12);
            fma2(acc[0][0], pa, v0.x); fma2(acc[0][1], pa, v0.y);
            fma2(acc[0][2], pa, v1.x); fma2(acc[0][3], pa, v1.y);
            fma2(acc[0][4], pa, v2.x); fma2(acc[0][5], pa, v2.y);
            fma2(acc[0][6], pa, v3.x); fma2(acc[0][7], pa, v3.y);
            fma2(acc[1][0], pb, v0.x); fma2(acc[1][1], pb, v0.y);
            fma2(acc[1][2], pb, v1.x); fma2(acc[1][3], pb, v1.y);
            fma2(acc[1][4], pb, v2.x); fma2(acc[1][5], pb, v2.y);
            fma2(acc[1][6], pb, v3.x); fma2(acc[1][7], pb, v3.y);
        }
    }

    // reduce over the 8 key-subgroups (lanes differing in bits 2..4)
    float2 f[2][8];
    #pragma unroll
    for (int r = 0; r < 2; ++r)
        #pragma unroll
        for (int p = 0; p < 8; ++p) f[r][p] = unpack2(acc[r][p]);

    #pragma unroll
    for (int off = 4; off <= 16; off <<= 1) {
        #pragma unroll
        for (int r = 0; r < 2; ++r)
            #pragma unroll
            for (int p = 0; p < 8; ++p) {
                f[r][p].x += __shfl_xor_sync(0xffffffffu, f[r][p].x, off);
                f[r][p].y += __shfl_xor_sync(0xffffffffu, f[r][p].y, off);
            }
    }

    if (kgv == 0) {
        float* obase = out + (size_t)bh * SS * DVV + (size_t)q0 * DVV;
        #pragma unroll
        for (int r = 0; r < 2; ++r) {
            float* orow = obase + (2 * w + r) * DVV + dg * 16;
            #pragma unroll
            for (int p = 0; p < 8; ++p)
                *(float2*)(orow + 2 * p) = f[r][p];
        }
    }
}

extern "C" void kernel_launch(void* const* d_in, const int* in_sizes, int n_in,
                              void* d_out, int out_size)
{
    const float* q    = (const float*)d_in[0];
    const float* k    = (const float*)d_in[1];
    const float* v    = (const float*)d_in[2];
    const int*   mask = (const int*)d_in[3];

    float* out  = (float*)d_out;
    float* attn = out + (size_t)BB * HH * SS * DVV;

    static bool configured = false;
    if (!configured) {
        cudaFuncSetAttribute(psdpa_kernel,
                             cudaFuncAttributeMaxDynamicSharedMemorySize,
                             SMEM_FLOATS * sizeof(float));
        configured = true;
    }

    dim3 grid(SS / SBLK, BB * HH);
    psdpa_kernel<<<grid, NTHREADS, SMEM_FLOATS * sizeof(float)>>>(
        q, k, v, mask, out, attn);
}

// round 4
// speedup vs baseline: 4.3896x; 4.3896x over previous
#include <cuda_runtime.h>
#include <cuda_bf16.h>
#include <cstdint>

#define BB 4
#define HH 16
#define SS 2048
#define DD 64

#define TM 64          // q rows per CTA
#define KT 64          // keys per tile
#define NTILES (SS / KT)
#define NTHREADS 256
#define KST 72         // smem row stride in halves (144B): conflict-free frag loads

__device__ float g_zinv[BB * HH * SS];   // 512 KB scratch (allowed: __device__ global)

// ---------------- fast 2^y (FFMA only), rel err ~2e-6 ----------------
__device__ __forceinline__ float fexp2f(float y) {
    y = fmaxf(y, -125.0f);
    float t = y + 12582912.0f;               // round-to-int via 1.5*2^23
    int   i = __float_as_int(t) << 23;
    float f = y - (t - 12582912.0f);
    float r = 1.3333558e-3f;
    r = fmaf(r, f, 9.6181291e-3f);
    r = fmaf(r, f, 5.5504109e-2f);
    r = fmaf(r, f, 2.4022651e-1f);
    r = fmaf(r, f, 6.9314718e-1f);
    r = fmaf(r, f, 1.0f);
    return __int_as_float(__float_as_int(r) + i);
}
#define L2E  1.4426950408889634f
#define SHL2 11.541560327111707f   // 8*log2(e):  exp(s-8) = 2^(s*L2E - SHL2)

// ---------------- mma / ldmatrix wrappers ----------------
__device__ __forceinline__ void mma16816(float* c, const uint32_t* a, uint32_t b0, uint32_t b1) {
    asm volatile(
        "mma.sync.aligned.m16n8k16.row.col.f32.bf16.bf16.f32 "
        "{%0,%1,%2,%3},{%4,%5,%6,%7},{%8,%9},{%0,%1,%2,%3};"
        : "+f"(c[0]), "+f"(c[1]), "+f"(c[2]), "+f"(c[3])
        : "r"(a[0]), "r"(a[1]), "r"(a[2]), "r"(a[3]), "r"(b0), "r"(b1));
}
__device__ __forceinline__ void ldsm_x2_trans(uint32_t& r0, uint32_t& r1, uint32_t addr) {
    asm volatile("ldmatrix.sync.aligned.m8n8.x2.trans.shared.b16 {%0,%1}, [%2];"
                 : "=r"(r0), "=r"(r1) : "r"(addr));
}
__device__ __forceinline__ uint32_t pack_bf16(float x, float y) {
    __nv_bfloat162 h = __floats2bfloat162_rn(x, y);
    return *(uint32_t*)&h;
}

// stage [64 keys][64 d] f32 -> bf16 hi/lo smem rows of stride KST halves
__device__ __forceinline__ void stage_bf16(uint16_t* hi, uint16_t* lo,
                                           const float* src, int tid) {
    const float4* g = (const float4*)src;
    #pragma unroll
    for (int it = 0; it < 4; ++it) {
        int idx = tid + it * NTHREADS;
        int key = idx >> 4;
        int d4  = (idx & 15) << 2;
        float4 x = g[idx];
        uint32_t h01 = pack_bf16(x.x, x.y);
        uint32_t h23 = pack_bf16(x.z, x.w);
        float l0 = x.x - __bfloat162float(((__nv_bfloat162*)&h01)->x);
        float l1 = x.y - __bfloat162float(((__nv_bfloat162*)&h01)->y);
        float l2 = x.z - __bfloat162float(((__nv_bfloat162*)&h23)->x);
        float l3 = x.w - __bfloat162float(((__nv_bfloat162*)&h23)->y);
        uint32_t lo01 = pack_bf16(l0, l1);
        uint32_t lo23 = pack_bf16(l2, l3);
        *(uint2*)(hi + key * KST + d4) = make_uint2(h01, h23);
        *(uint2*)(lo + key * KST + d4) = make_uint2(lo01, lo23);
    }
}

__global__ __launch_bounds__(NTHREADS, 1)
void psdpa_mma_kernel(const float* __restrict__ q,
                      const float* __restrict__ k,
                      const float* __restrict__ v,
                      const int* __restrict__ mask,
                      float* __restrict__ out,
                      float* __restrict__ attn)
{
    __shared__ uint16_t Khi[KT * KST], Klo[KT * KST];
    __shared__ uint16_t Vhi[KT * KST], Vlo[KT * KST];
    __shared__ float Zbuf[2 * TM];
    __shared__ float invZs[TM];

    const int tid  = threadIdx.x;
    const int w    = tid >> 5;
    const int lane = tid & 31;
    const int wr   = w & 3;        // row group (16 rows each)
    const int wc   = w >> 2;       // key-column half (32 keys each)
    const int g    = lane >> 2;
    const int j2   = (lane & 3) << 1;

    const int bh = blockIdx.y;
    const int b  = bh >> 4;
    const int q0 = blockIdx.x * TM;

    const float* qbase = q + ((size_t)bh * SS + q0) * DD;
    const float* kbase = k + (size_t)bh * SS * DD;
    const float* vbase = v + (size_t)bh * SS * DD;

    // ---- Q fragments (scaled 1/8), hi/lo split: reuse V smem as f32 staging ----
    uint32_t qhi[4][4], qlo[4][4];
    {
        float* Qtmp = (float*)Vhi;   // 16 KB fits in Vhi+Vlo (36 KB)
        const float4* qg = (const float4*)qbase;
        #pragma unroll
        for (int it = 0; it < 4; ++it) {
            int idx = tid + it * NTHREADS;
            int row = idx >> 4;
            int d4  = (idx & 15) << 2;
            float4 x = qg[idx];
            x.x *= 0.125f; x.y *= 0.125f; x.z *= 0.125f; x.w *= 0.125f;
            *(float4*)(Qtmp + row * DD + d4) = x;
        }
        __syncthreads();
        const int r0 = wr * 16 + g, r1 = r0 + 8;
        #pragma unroll
        for (int ks = 0; ks < 4; ++ks) {
            int d0 = ks * 16 + j2, d1 = d0 + 8;
            float2 x0 = *(float2*)(Qtmp + r0 * DD + d0);
            float2 x1 = *(float2*)(Qtmp + r1 * DD + d0);
            float2 x2 = *(float2*)(Qtmp + r0 * DD + d1);
            float2 x3 = *(float2*)(Qtmp + r1 * DD + d1);
            qhi[ks][0] = pack_bf16(x0.x, x0.y);
            qhi[ks][1] = pack_bf16(x1.x, x1.y);
            qhi[ks][2] = pack_bf16(x2.x, x2.y);
            qhi[ks][3] = pack_bf16(x3.x, x3.y);
            qlo[ks][0] = pack_bf16(x0.x - __bfloat162float(((__nv_bfloat162*)&qhi[ks][0])->x),
                                   x0.y - __bfloat162float(((__nv_bfloat162*)&qhi[ks][0])->y));
            qlo[ks][1] = pack_bf16(x1.x - __bfloat162float(((__nv_bfloat162*)&qhi[ks][1])->x),
                                   x1.y - __bfloat162float(((__nv_bfloat162*)&qhi[ks][1])->y));
            qlo[ks][2] = pack_bf16(x2.x - __bfloat162float(((__nv_bfloat162*)&qhi[ks][2])->x),
                                   x2.y - __bfloat162float(((__nv_bfloat162*)&qhi[ks][2])->y));
            qlo[ks][3] = pack_bf16(x3.x - __bfloat162float(((__nv_bfloat162*)&qhi[ks][3])->x),
                                   x3.y - __bfloat162float(((__nv_bfloat162*)&qhi[ks][3])->y));
        }
    }

    const int qrow0 = q0 + wr * 16 + g;
    const int qrow8 = qrow0 + 8;
    const int* mrow0 = mask + ((size_t)b * SS + qrow0) * SS;
    const int* mrow8 = mask + ((size_t)b * SS + qrow8) * SS;
    float* arow0 = attn + ((size_t)bh * SS + qrow0) * SS;
    float* arow8 = attn + ((size_t)bh * SS + qrow8) * SS;

    // ldmatrix per-lane base address into V tiles (row = key, 16B block = 8 d)
    const int lkey = lane & 15;
    const uint32_t vhi_base = (uint32_t)__cvta_generic_to_shared(Vhi) + ((wc * 32 + lkey) * KST) * 2;
    const uint32_t vlo_base = (uint32_t)__cvta_generic_to_shared(Vlo) + ((wc * 32 + lkey) * KST) * 2;

    float O[8][4];
    #pragma unroll
    for (int i = 0; i < 8; ++i)
        #pragma unroll
        for (int c = 0; c < 4; ++c) O[i][c] = 0.0f;
    float Zp0 = 0.0f, Zp1 = 0.0f;

    for (int t = 0; t < NTILES; ++t) {
        __syncthreads();
        stage_bf16(Khi, Klo, kbase + (size_t)t * KT * DD, tid);
        stage_bf16(Vhi, Vlo, vbase + (size_t)t * KT * DD, tid);
        __syncthreads();

        // ---------------- QK^T : S[4 n8][4] over 32 keys ----------------
        float S[4][4];
        #pragma unroll
        for (int i = 0; i < 4; ++i)
            #pragma unroll
            for (int c = 0; c < 4; ++c) S[i][c] = 0.0f;

        #pragma unroll
        for (int ks = 0; ks < 4; ++ks) {
            uint32_t bh0[4], bh1[4], bl0[4], bl1[4];
            #pragma unroll
            for (int n8 = 0; n8 < 4; ++n8) {
                int key = wc * 32 + n8 * 8 + g;
                int d   = ks * 16 + j2;
                bh0[n8] = *(uint32_t*)(Khi + key * KST + d);
                bh1[n8] = *(uint32_t*)(Khi + key * KST + d + 8);
                bl0[n8] = *(uint32_t*)(Klo + key * KST + d);
                bl1[n8] = *(uint32_t*)(Klo + key * KST + d + 8);
            }
            #pragma unroll
            for (int n8 = 0; n8 < 4; ++n8) mma16816(S[n8], qhi[ks], bh0[n8], bh1[n8]);
            #pragma unroll
            for (int n8 = 0; n8 < 4; ++n8) mma16816(S[n8], qlo[ks], bh0[n8], bh1[n8]);
            #pragma unroll
            for (int n8 = 0; n8 < 4; ++n8) mma16816(S[n8], qhi[ks], bl0[n8], bl1[n8]);
        }

        // ---------------- mask + exp + attn store + Z + P frags ----------------
        uint32_t phi[2][4], plo[2][4];
        #pragma unroll
        for (int gi = 0; gi < 4; ++gi) {
            int cb = t * KT + wc * 32 + gi * 8 + j2;
            int2 m0 = *(const int2*)(mrow0 + cb);
            int2 m8 = *(const int2*)(mrow8 + cb);
            float e0 = (m0.x != 0) ? fexp2f(fmaf(S[gi][0], L2E, -SHL2)) : 0.0f;
            float e1 = (m0.y != 0) ? fexp2f(fmaf(S[gi][1], L2E, -SHL2)) : 0.0f;
            float e2 = (m8.x != 0) ? fexp2f(fmaf(S[gi][2], L2E, -SHL2)) : 0.0f;
            float e3 = (m8.y != 0) ? fexp2f(fmaf(S[gi][3], L2E, -SHL2)) : 0.0f;
            *(float2*)(arow0 + cb) = make_float2(e0, e1);
            *(float2*)(arow8 + cb) = make_float2(e2, e3);
            Zp0 += e0 + e1;
            Zp1 += e2 + e3;
            int kc = gi >> 1, hh = (gi & 1) << 1;
            uint32_t h01 = pack_bf16(e0, e1);
            uint32_t h23 = pack_bf16(e2, e3);
            phi[kc][hh + 0] = h01;
            phi[kc][hh + 1] = h23;
            plo[kc][hh + 0] = pack_bf16(e0 - __bfloat162float(((__nv_bfloat162*)&h01)->x),
                                        e1 - __bfloat162float(((__nv_bfloat162*)&h01)->y));
            plo[kc][hh + 1] = pack_bf16(e2 - __bfloat162float(((__nv_bfloat162*)&h23)->x),
                                        e3 - __bfloat162float(((__nv_bfloat162*)&h23)->y));
        }

        // ---------------- P @ V : O[8 dn8][4] ----------------
        #pragma unroll
        for (int kc = 0; kc < 2; ++kc) {
            #pragma unroll
            for (int dn8 = 0; dn8 < 8; ++dn8) {
                uint32_t vh0, vh1, vl0, vl1;
                ldsm_x2_trans(vh0, vh1, vhi_base + (kc * 16 * KST + dn8 * 8) * 2);
                ldsm_x2_trans(vl0, vl1, vlo_base + (kc * 16 * KST + dn8 * 8) * 2);
                mma16816(O[dn8], phi[kc], vh0, vh1);
                mma16816(O[dn8], plo[kc], vh0, vh1);
                mma16816(O[dn8], phi[kc], vl0, vl1);
            }
        }
    }

    // ---------------- epilogue: Z reduce, O reduce, write out ----------------
    Zp0 += __shfl_xor_sync(0xffffffffu, Zp0, 1);
    Zp0 += __shfl_xor_sync(0xffffffffu, Zp0, 2);
    Zp1 += __shfl_xor_sync(0xffffffffu, Zp1, 1);
    Zp1 += __shfl_xor_sync(0xffffffffu, Zp1, 2);
    __syncthreads();              // all tiles done using smem
    if ((lane & 3) == 0) {
        Zbuf[wc * TM + wr * 16 + g]     = Zp0;
        Zbuf[wc * TM + wr * 16 + g + 8] = Zp1;
    }
    __syncthreads();
    if (tid < TM) {
        float iz = 1.0f / (Zbuf[tid] + Zbuf[TM + tid]);
        invZs[tid] = iz;
        g_zinv[(size_t)bh * SS + q0 + tid] = iz;
    }

    float* Obuf = (float*)Khi;    // [64][68] f32 = 17408 B, fits Khi+Klo
    const int r0 = wr * 16 + g, r1 = r0 + 8;
    if (wc == 0) {
        #pragma unroll
        for (int dn8 = 0; dn8 < 8; ++dn8) {
            *(float2*)(Obuf + r0 * 68 + dn8 * 8 + j2) = make_float2(O[dn8][0], O[dn8][1]);
            *(float2*)(Obuf + r1 * 68 + dn8 * 8 + j2) = make_float2(O[dn8][2], O[dn8][3]);
        }
    }
    __syncthreads();
    if (wc == 1) {
        #pragma unroll
        for (int dn8 = 0; dn8 < 8; ++dn8) {
            float2* p0 = (float2*)(Obuf + r0 * 68 + dn8 * 8 + j2);
            float2* p1 = (float2*)(Obuf + r1 * 68 + dn8 * 8 + j2);
            float2 a0 = *p0, a1 = *p1;
            a0.x += O[dn8][0]; a0.y += O[dn8][1];
            a1.x += O[dn8][2]; a1.y += O[dn8][3];
            *p0 = a0; *p1 = a1;
        }
    }
    __syncthreads();
    {
        int row = tid >> 2;
        int dq  = (tid & 3) * 16;
        float iz = invZs[row];
        float* orow = out + ((size_t)bh * SS + q0 + row) * DD + dq;
        #pragma unroll
        for (int i = 0; i < 4; ++i) {
            float4 x = *(float4*)(Obuf + row * 68 + dq + i * 4);
            x.x *= iz; x.y *= iz; x.z *= iz; x.w *= iz;
            *(float4*)(orow + i * 4) = x;
        }
    }
}

// kernel 2: attn[row][*] *= zinv[row]
__global__ __launch_bounds__(256)
void attn_norm_kernel(float* __restrict__ attn)
{
    size_t i = (size_t)blockIdx.x * blockDim.x + threadIdx.x;   // float4 index
    float4* a4 = (float4*)attn;
    float iz = __ldg(&g_zinv[i >> 9]);      // 512 float4 per row
    float4 x = a4[i];
    x.x *= iz; x.y *= iz; x.z *= iz; x.w *= iz;
    a4[i] = x;
}

extern "C" void kernel_launch(void* const* d_in, const int* in_sizes, int n_in,
                              void* d_out, int out_size)
{
    const float* q    = (const float*)d_in[0];
    const float* k    = (const float*)d_in[1];
    const float* v    = (const float*)d_in[2];
    const int*   mask = (const int*)d_in[3];

    float* out  = (float*)d_out;
    float* attn = out + (size_t)BB * HH * SS * DD;

    dim3 grid1(SS / TM, BB * HH);
    psdpa_mma_kernel<<<grid1, NTHREADS>>>(q, k, v, mask, out, attn);

    size_t n4 = (size_t)BB * HH * SS * SS / 4;
    attn_norm_kernel<<<(unsigned)(n4 / 256), 256>>>(attn);
}